// round 8
// baseline (speedup 1.0000x reference)
#include <cuda_runtime.h>
#include <cstdint>

#define NP    64                 // patch size
#define CH    4                  // channels
#define PAD   192                // canvas
#define TPB   512
#define CPIX  (PAD*PAD)          // 36864 floats
#define CBYTES (CPIX*4)          // 147456 bytes
#define GPOS  (65*65)            // G positions per channel

__device__ __forceinline__ uint32_t smem_u32(const void* p) {
    uint32_t a;
    asm("{ .reg .u64 t; cvta.to.shared.u64 t, %1; cvt.u32.u64 %0, t; }"
        : "=r"(a) : "l"(p));
    return a;
}

// out[b,y,x] = sum_c bilinear(patch_c centered, y-64-dy_c, x-64-dx_c), zero fill.
// Integer pixel coords => bilinear weights constant per (b,c):
//   out(y,x) = sum_c G_c[y+oyc+1][x+oxc+1],  G_c = 2x2 corr(patch_c, weights).
// Inverted dataflow: scatter-add each G_c(gy,gxi) into a full smem canvas at
// (gy-1-oyc, gxi-1-oxc) — always in [0,191] since |offset|<=63 — then one TMA
// bulk copy smem->gmem. No per-pixel channel tests, no gather loop.
__global__ __launch_bounds__(TPB, 1)
void reassemble_scatter_kernel(const float* __restrict__ patches,
                               const float* __restrict__ pos,
                               float* __restrict__ out)
{
    extern __shared__ float canvas[];    // PAD*PAD floats = 147,456 B
    const int b   = blockIdx.x;
    const int tid = threadIdx.x;

    // ---- zero canvas (STS.128) ----
    float4* cv = reinterpret_cast<float4*>(canvas);
    #pragma unroll
    for (int i = tid; i < CPIX / 4; i += TPB)        // 18 iters
        cv[i] = make_float4(0.f, 0.f, 0.f, 0.f);

    // ---- per-channel integer offsets + constant bilinear weights ----
    int   ox[CH], oy[CH];
    float w00[CH], w01[CH], w10[CH], w11[CH];
    const float* pb_pos = pos + (size_t)b * 2 * CH;
    #pragma unroll
    for (int c = 0; c < CH; c++) {
        const float dx = __ldg(pb_pos + c);
        const float dy = __ldg(pb_pos + CH + c);
        const float fx = -64.0f - dx;
        const float fy = -64.0f - dy;
        const float flx = floorf(fx), fly = floorf(fy);
        ox[c] = (int)flx;
        oy[c] = (int)fly;
        const float wx = fx - flx, wy = fy - fly;
        w00[c] = (1.0f - wx) * (1.0f - wy);
        w01[c] = wx * (1.0f - wy);
        w10[c] = (1.0f - wx) * wy;
        w11[c] = wx * wy;
    }
    __syncthreads();

    // ---- build + scatter: one pass over 65x65 G positions ----
    // taps shared across all 4 channels (float4 loads); destinations differ.
    const float4* pin = reinterpret_cast<const float4*>(patches + (size_t)b * NP * NP * CH);
    for (int idx = tid; idx < GPOS; idx += TPB) {    // ~8.25 iters
        const int gy  = idx / 65;                    // 0..64
        const int gxi = idx - gy * 65;               // 0..64
        const int iy  = gy - 1;
        const int ix  = gxi - 1;

        const bool r0 = (gy >= 1), r1 = (gy <= 63);
        const bool c0 = (gxi >= 1), c1 = (gxi <= 63);
        const float4 z = make_float4(0.f, 0.f, 0.f, 0.f);
        const float4 t00 = (r0 && c0) ? __ldg(pin + iy * NP + ix)     : z;
        const float4 t01 = (r0 && c1) ? __ldg(pin + iy * NP + ix + 1) : z;
        const float4 t10 = (r1 && c0) ? __ldg(pin + gy * NP + ix)     : z;
        const float4 t11 = (r1 && c1) ? __ldg(pin + gy * NP + ix + 1) : z;

        // per-channel G value and scatter destination (always in-bounds)
        const float g0 = t00.x * w00[0] + t01.x * w01[0] + t10.x * w10[0] + t11.x * w11[0];
        const float g1 = t00.y * w00[1] + t01.y * w01[1] + t10.y * w10[1] + t11.y * w11[1];
        const float g2 = t00.z * w00[2] + t01.z * w01[2] + t10.z * w10[2] + t11.z * w11[2];
        const float g3 = t00.w * w00[3] + t01.w * w01[3] + t10.w * w10[3] + t11.w * w11[3];

        atomicAdd(canvas + (gy - 1 - oy[0]) * PAD + (gxi - 1 - ox[0]), g0);
        atomicAdd(canvas + (gy - 1 - oy[1]) * PAD + (gxi - 1 - ox[1]), g1);
        atomicAdd(canvas + (gy - 1 - oy[2]) * PAD + (gxi - 1 - ox[2]), g2);
        atomicAdd(canvas + (gy - 1 - oy[3]) * PAD + (gxi - 1 - ox[3]), g3);
    }
    __syncthreads();

    // ---- single TMA bulk copy: smem canvas -> global out ----
    asm volatile("fence.proxy.async.shared::cta;" ::: "memory");
    if (tid == 0) {
        const uint32_t s = smem_u32(canvas);
        float* gdst = out + (size_t)b * CPIX;
        asm volatile("cp.async.bulk.global.shared::cta.bulk_group [%0], [%1], %2;"
                     :: "l"(gdst), "r"(s), "r"((uint32_t)CBYTES) : "memory");
        asm volatile("cp.async.bulk.commit_group;" ::: "memory");
        asm volatile("cp.async.bulk.wait_group 0;" ::: "memory");
    }
}

extern "C" void kernel_launch(void* const* d_in, const int* in_sizes, int n_in,
                              void* d_out, int out_size) {
    const float* patches = (const float*)d_in[0];   // (B, 64, 64, 4) fp32
    const float* pos     = (const float*)d_in[1];   // (B, 1, 2, 4)  fp32
    float* out           = (float*)d_out;           // (B, 192, 192, 1) fp32

    const int B = out_size / CPIX;                  // 512
    static bool attr_set = false;
    if (!attr_set) {
        cudaFuncSetAttribute(reassemble_scatter_kernel,
                             cudaFuncAttributeMaxDynamicSharedMemorySize, CBYTES);
        attr_set = true;
    }
    reassemble_scatter_kernel<<<B, TPB, CBYTES>>>(patches, pos, out);
}

// round 9
// speedup vs baseline: 1.5333x; 1.5333x over previous
#include <cuda_runtime.h>

#define NP    64                 // patch size
#define CH    4                  // channels
#define PAD   192                // canvas
#define TPB   576                // 48 quad-cols x 12 rows
#define PLW   76                 // G plane width (zero borders both sides)
#define PLH   65                 // G rows: iy+1 in [0,64]
#define PLANE (PLW*PLH)          // 4940 floats
#define SMF   (CH*PLANE)         // 19760 floats = 79,040 B
#define GIN   (63*63)            // interior G positions per channel
#define GBRD  256                // border G positions per channel
#define ZVEC  (CH*PLH*4)         // border zero float4s: cols [0,7] & [68,75]
#define YSTEP (TPB/(PAD/4))      // 12
#define EITER (PAD/YSTEP)        // 16 eval iterations

// out[b,y,x] = sum_c bilinear(patch_c centered, y-64-dy_c, x-64-dx_c), zero fill.
// Integer pixel coords => bilinear weights constant per (b,c):
//   out(y,x) = G_c[y+oyc+1][x+oxc+...], G_c = 2x2 corr(patch_c, weights).
// G built once per sample in smem; eval uses a fixed column per thread so the
// x-validity test and index decode hoist out of the loop.
__global__ __launch_bounds__(TPB, 2)
void reassemble_fixcol_kernel(const float* __restrict__ patches,
                              const float* __restrict__ pos,
                              float* __restrict__ out)
{
    extern __shared__ float sm[];        // CH planes of [PLH][PLW]
    const int b   = blockIdx.x;
    const int tid = threadIdx.x;

    // ---- per-channel constants ----
    int   oxc[CH], shf[CH], off0[CH], oyc[CH];
    float w00[CH], w01[CH], w10[CH], w11[CH];
    const float* pb_pos = pos + (size_t)b * 2 * CH;
    #pragma unroll
    for (int c = 0; c < CH; c++) {
        const float dx = __ldg(pb_pos + c);
        const float dy = __ldg(pb_pos + CH + c);
        const float fx = -64.0f - dx;
        const float fy = -64.0f - dy;
        const float flx = floorf(fx), fly = floorf(fy);
        oxc[c] = (int)flx;
        oyc[c] = (int)fly;
        shf[c] = (4 - (oxc[c] & 3)) & 3;              // (oxc+shf) % 4 == 0
        off0[c] = c * PLANE + (oyc[c] + 1) * PLW + oxc[c] + shf[c] + 4;
        const float wx = fx - flx, wy = fy - fly;
        w00[c] = (1.0f - wx) * (1.0f - wy);
        w01[c] = wx * (1.0f - wy);
        w10[c] = (1.0f - wx) * wy;
        w11[c] = wx * wy;
    }

    // ---- zero border columns: cols [0,7] and [68,75] of every row ----
    {
        float4* smv = reinterpret_cast<float4*>(sm);
        #pragma unroll
        for (int i = tid; i < ZVEC; i += TPB) {        // 1040 vecs -> 2 iters
            const int plane = i / (PLH * 4);
            const int rem   = i - plane * (PLH * 4);
            const int row   = rem >> 2;
            const int v     = rem & 3;
            const int col4  = (v < 2) ? (v << 2) : (68 + ((v - 2) << 2));
            smv[(plane * PLANE + row * PLW + col4) >> 2] = make_float4(0.f, 0.f, 0.f, 0.f);
        }
    }
    __syncthreads();

    // ---- build G planes: interior (no tap guards) ----
    const float4* pin = reinterpret_cast<const float4*>(patches + (size_t)b * NP * NP * CH);
    for (int idx = tid; idx < GIN; idx += TPB) {       // ~6.9 iters
        const int r   = idx / 63;                      // 0..62
        const int gxi = idx - r * 63 + 1;              // 1..63
        const int gy  = r + 1;                         // 1..63
        const int ix  = gxi - 1;

        const float4 t00 = __ldg(pin + (gy - 1) * NP + ix);
        const float4 t01 = __ldg(pin + (gy - 1) * NP + ix + 1);
        const float4 t10 = __ldg(pin + gy * NP + ix);
        const float4 t11 = __ldg(pin + gy * NP + ix + 1);

        const int rb = gy * PLW + gxi + 3;
        sm[0 * PLANE + rb + shf[0]] = t00.x * w00[0] + t01.x * w01[0] + t10.x * w10[0] + t11.x * w11[0];
        sm[1 * PLANE + rb + shf[1]] = t00.y * w00[1] + t01.y * w01[1] + t10.y * w10[1] + t11.y * w11[1];
        sm[2 * PLANE + rb + shf[2]] = t00.z * w00[2] + t01.z * w01[2] + t10.z * w10[2] + t11.z * w11[2];
        sm[3 * PLANE + rb + shf[3]] = t00.w * w00[3] + t01.w * w01[3] + t10.w * w10[3] + t11.w * w11[3];
    }

    // ---- build G planes: 256 border positions (guarded taps) ----
    if (tid < GBRD) {
        int gy, gxi;
        if (tid < 65)       { gy = 0;         gxi = tid; }
        else if (tid < 130) { gy = 64;        gxi = tid - 65; }
        else if (tid < 193) { gy = tid - 129; gxi = 0;  }   // 1..63
        else                { gy = tid - 192; gxi = 64; }   // 1..63
        const int iy = gy - 1;
        const int ix = gxi - 1;
        const bool r0 = (gy >= 1), r1 = (gy <= 63);
        const bool c0 = (gxi >= 1), c1 = (gxi <= 63);
        const float4 z = make_float4(0.f, 0.f, 0.f, 0.f);
        const float4 t00 = (r0 && c0) ? __ldg(pin + iy * NP + ix)     : z;
        const float4 t01 = (r0 && c1) ? __ldg(pin + iy * NP + ix + 1) : z;
        const float4 t10 = (r1 && c0) ? __ldg(pin + gy * NP + ix)     : z;
        const float4 t11 = (r1 && c1) ? __ldg(pin + gy * NP + ix + 1) : z;

        const int rb = gy * PLW + gxi + 3;
        sm[0 * PLANE + rb + shf[0]] = t00.x * w00[0] + t01.x * w01[0] + t10.x * w10[0] + t11.x * w11[0];
        sm[1 * PLANE + rb + shf[1]] = t00.y * w00[1] + t01.y * w01[1] + t10.y * w10[1] + t11.y * w11[1];
        sm[2 * PLANE + rb + shf[2]] = t00.z * w00[2] + t01.z * w01[2] + t10.z * w10[2] + t11.z * w11[2];
        sm[3 * PLANE + rb + shf[3]] = t00.w * w00[3] + t01.w * w01[3] + t10.w * w10[3] + t11.w * w11[3];
    }
    __syncthreads();

    // ---- eval: fixed quad column per thread; y advances by YSTEP ----
    const int qcol = tid % (PAD / 4);                  // 0..47
    const int x0   = qcol * 4;
    int y = tid / (PAD / 4);                           // 0..11

    // per-channel loop-invariant: y-window lo (INT_MAX if x-invalid) + base
    int lo[CH], fb[CH];
    #pragma unroll
    for (int c = 0; c < CH; c++) {
        const int ix0 = x0 + oxc[c];
        const bool xok = ((unsigned)(ix0 + 4) <= 71u);  // ix0 in [-4,63]
        lo[c] = xok ? (-1 - oyc[c]) : 0x7FFFFFFF;       // iy = y+oy in [-1,63]
        fb[c] = off0[c] + x0;                           // float index base
    }

    float* po = out + (size_t)b * PAD * PAD + (size_t)y * PAD + x0;
    int ywf = y * PLW;

    #pragma unroll
    for (int q = 0; q < EITER; q++) {
        float a0 = 0.f, a1 = 0.f, a2 = 0.f, a3 = 0.f;

        #pragma unroll
        for (int c = 0; c < CH; c++) {
            if ((unsigned)(y - lo[c]) <= 64u) {
                const float4 g = *reinterpret_cast<const float4*>(sm + fb[c] + ywf);
                a0 += g.x; a1 += g.y; a2 += g.z; a3 += g.w;
            }
        }

        float4 o4; o4.x = a0; o4.y = a1; o4.z = a2; o4.w = a3;
        *reinterpret_cast<float4*>(po) = o4;

        y   += YSTEP;
        ywf += YSTEP * PLW;
        po  += YSTEP * PAD;
    }
}

extern "C" void kernel_launch(void* const* d_in, const int* in_sizes, int n_in,
                              void* d_out, int out_size) {
    const float* patches = (const float*)d_in[0];   // (B, 64, 64, 4) fp32
    const float* pos     = (const float*)d_in[1];   // (B, 1, 2, 4)  fp32
    float* out           = (float*)d_out;           // (B, 192, 192, 1) fp32

    const int B = out_size / (PAD * PAD);           // 512
    const int smem_bytes = SMF * sizeof(float);     // 79,040 B
    static bool attr_set = false;
    if (!attr_set) {
        cudaFuncSetAttribute(reassemble_fixcol_kernel,
                             cudaFuncAttributeMaxDynamicSharedMemorySize, smem_bytes);
        attr_set = true;
    }
    reassemble_fixcol_kernel<<<B, TPB, smem_bytes>>>(patches, pos, out);
}

// round 10
// speedup vs baseline: 1.6250x; 1.0598x over previous
#include <cuda_runtime.h>

#define NP    64                 // patch size
#define CH    4                  // channels
#define PAD   192                // canvas
#define TPB   576                // 24 quad-cols x 24 rows
#define PLW   76                 // G plane width (zero borders both sides)
#define PLH   65                 // G rows: iy+1 in [0,64]
#define PLANE (PLW*PLH)          // 4940 floats
#define SMF   (CH*PLANE)         // 19760 floats = 79,040 B
#define GIN   (63*63)            // interior G positions per channel
#define GBRD  256                // border G positions per channel
#define ZVEC  (CH*PLH*4)         // border zero float4s: cols [0,7] & [68,75]
#define QC    24                 // quad columns per thread-row (x and x+96)
#define YSTEP (TPB/QC)           // 24
#define EITER (PAD/YSTEP)        // 8 eval iterations

// out[b,y,x] = sum_c bilinear(patch_c centered, y-64-dy_c, x-64-dx_c), zero fill.
// Integer pixel coords => bilinear weights constant per (b,c):
//   out(y,x) = G_c[y+oyc+1][...], G_c = 2x2 corr(patch_c, weights), in smem.
// Eval: each thread owns TWO quads 96px apart (same y) -> shared y-test,
// 16B lane stride on both LDS.128 paths, 8 accumulators of ILP.
__global__ __launch_bounds__(TPB, 2)
void reassemble_2q_kernel(const float* __restrict__ patches,
                          const float* __restrict__ pos,
                          float* __restrict__ out)
{
    extern __shared__ float sm[];        // CH planes of [PLH][PLW]
    const int b   = blockIdx.x;
    const int tid = threadIdx.x;

    // ---- per-channel constants ----
    int   oxc[CH], shf[CH], off0[CH], oyc[CH];
    float w00[CH], w01[CH], w10[CH], w11[CH];
    const float* pb_pos = pos + (size_t)b * 2 * CH;
    #pragma unroll
    for (int c = 0; c < CH; c++) {
        const float dx = __ldg(pb_pos + c);
        const float dy = __ldg(pb_pos + CH + c);
        const float fx = -64.0f - dx;
        const float fy = -64.0f - dy;
        const float flx = floorf(fx), fly = floorf(fy);
        oxc[c] = (int)flx;
        oyc[c] = (int)fly;
        shf[c] = (4 - (oxc[c] & 3)) & 3;              // (oxc+shf) % 4 == 0
        off0[c] = c * PLANE + (oyc[c] + 1) * PLW + oxc[c] + shf[c] + 4;
        const float wx = fx - flx, wy = fy - fly;
        w00[c] = (1.0f - wx) * (1.0f - wy);
        w01[c] = wx * (1.0f - wy);
        w10[c] = (1.0f - wx) * wy;
        w11[c] = wx * wy;
    }

    // ---- zero border columns: cols [0,7] and [68,75] of every row ----
    {
        float4* smv = reinterpret_cast<float4*>(sm);
        #pragma unroll
        for (int i = tid; i < ZVEC; i += TPB) {        // 1040 vecs -> 2 iters
            const int plane = i / (PLH * 4);
            const int rem   = i - plane * (PLH * 4);
            const int row   = rem >> 2;
            const int v     = rem & 3;
            const int col4  = (v < 2) ? (v << 2) : (68 + ((v - 2) << 2));
            smv[(plane * PLANE + row * PLW + col4) >> 2] = make_float4(0.f, 0.f, 0.f, 0.f);
        }
    }
    __syncthreads();

    // ---- build G planes: interior (no tap guards) ----
    const float4* pin = reinterpret_cast<const float4*>(patches + (size_t)b * NP * NP * CH);
    for (int idx = tid; idx < GIN; idx += TPB) {       // ~6.9 iters
        const int r   = idx / 63;                      // 0..62
        const int gxi = idx - r * 63 + 1;              // 1..63
        const int gy  = r + 1;                         // 1..63
        const int ix  = gxi - 1;

        const float4 t00 = __ldg(pin + (gy - 1) * NP + ix);
        const float4 t01 = __ldg(pin + (gy - 1) * NP + ix + 1);
        const float4 t10 = __ldg(pin + gy * NP + ix);
        const float4 t11 = __ldg(pin + gy * NP + ix + 1);

        const int rb = gy * PLW + gxi + 3;
        sm[0 * PLANE + rb + shf[0]] = t00.x * w00[0] + t01.x * w01[0] + t10.x * w10[0] + t11.x * w11[0];
        sm[1 * PLANE + rb + shf[1]] = t00.y * w00[1] + t01.y * w01[1] + t10.y * w10[1] + t11.y * w11[1];
        sm[2 * PLANE + rb + shf[2]] = t00.z * w00[2] + t01.z * w01[2] + t10.z * w10[2] + t11.z * w11[2];
        sm[3 * PLANE + rb + shf[3]] = t00.w * w00[3] + t01.w * w01[3] + t10.w * w10[3] + t11.w * w11[3];
    }

    // ---- build G planes: 256 border positions (guarded taps) ----
    if (tid < GBRD) {
        int gy, gxi;
        if (tid < 65)       { gy = 0;         gxi = tid; }
        else if (tid < 130) { gy = 64;        gxi = tid - 65; }
        else if (tid < 193) { gy = tid - 129; gxi = 0;  }   // 1..63
        else                { gy = tid - 192; gxi = 64; }   // 1..63
        const int iy = gy - 1;
        const int ix = gxi - 1;
        const bool r0 = (gy >= 1), r1 = (gy <= 63);
        const bool c0 = (gxi >= 1), c1 = (gxi <= 63);
        const float4 z = make_float4(0.f, 0.f, 0.f, 0.f);
        const float4 t00 = (r0 && c0) ? __ldg(pin + iy * NP + ix)     : z;
        const float4 t01 = (r0 && c1) ? __ldg(pin + iy * NP + ix + 1) : z;
        const float4 t10 = (r1 && c0) ? __ldg(pin + gy * NP + ix)     : z;
        const float4 t11 = (r1 && c1) ? __ldg(pin + gy * NP + ix + 1) : z;

        const int rb = gy * PLW + gxi + 3;
        sm[0 * PLANE + rb + shf[0]] = t00.x * w00[0] + t01.x * w01[0] + t10.x * w10[0] + t11.x * w11[0];
        sm[1 * PLANE + rb + shf[1]] = t00.y * w00[1] + t01.y * w01[1] + t10.y * w10[1] + t11.y * w11[1];
        sm[2 * PLANE + rb + shf[2]] = t00.z * w00[2] + t01.z * w01[2] + t10.z * w10[2] + t11.z * w11[2];
        sm[3 * PLANE + rb + shf[3]] = t00.w * w00[3] + t01.w * w01[3] + t10.w * w10[3] + t11.w * w11[3];
    }
    __syncthreads();

    // ---- eval: two quads per thread (x0a and x0a+96), same y ----
    const int qcol = tid % QC;                          // 0..23
    const int x0a  = qcol * 4;                          // 0..92
    const int x0b  = x0a + 96;                          // 96..188
    int y = tid / QC;                                   // 0..23

    // per-channel loop-invariant: y-window lower bound per quad
    // (INT_MAX when that quad's x is outside the channel window)
    int loa[CH], lob[CH], fba[CH];
    #pragma unroll
    for (int c = 0; c < CH; c++) {
        const int ixa = x0a + oxc[c];
        const int ixb = x0b + oxc[c];
        const int ywlo = -1 - oyc[c];                   // iy = y+oy in [-1,63]
        loa[c] = ((unsigned)(ixa + 4) <= 71u) ? ywlo : 0x7FFFFFFF;
        lob[c] = ((unsigned)(ixb + 4) <= 71u) ? ywlo : 0x7FFFFFFF;
        fba[c] = off0[c] + x0a;                         // quad-b base = +96
    }

    float* po = out + (size_t)b * PAD * PAD + (size_t)y * PAD + x0a;
    int ywf = y * PLW;

    #pragma unroll
    for (int q = 0; q < EITER; q++) {
        float a0 = 0.f, a1 = 0.f, a2 = 0.f, a3 = 0.f;
        float b0 = 0.f, b1 = 0.f, b2 = 0.f, b3 = 0.f;

        #pragma unroll
        for (int c = 0; c < CH; c++) {
            const int base = fba[c] + ywf;
            if ((unsigned)(y - loa[c]) <= 64u) {
                const float4 g = *reinterpret_cast<const float4*>(sm + base);
                a0 += g.x; a1 += g.y; a2 += g.z; a3 += g.w;
            }
            if ((unsigned)(y - lob[c]) <= 64u) {
                const float4 g = *reinterpret_cast<const float4*>(sm + base + 96);
                b0 += g.x; b1 += g.y; b2 += g.z; b3 += g.w;
            }
        }

        float4 oA; oA.x = a0; oA.y = a1; oA.z = a2; oA.w = a3;
        float4 oB; oB.x = b0; oB.y = b1; oB.z = b2; oB.w = b3;
        *reinterpret_cast<float4*>(po)      = oA;
        *reinterpret_cast<float4*>(po + 96) = oB;

        y   += YSTEP;
        ywf += YSTEP * PLW;
        po  += YSTEP * PAD;
    }
}

extern "C" void kernel_launch(void* const* d_in, const int* in_sizes, int n_in,
                              void* d_out, int out_size) {
    const float* patches = (const float*)d_in[0];   // (B, 64, 64, 4) fp32
    const float* pos     = (const float*)d_in[1];   // (B, 1, 2, 4)  fp32
    float* out           = (float*)d_out;           // (B, 192, 192, 1) fp32

    const int B = out_size / (PAD * PAD);           // 512
    const int smem_bytes = SMF * sizeof(float);     // 79,040 B
    static bool attr_set = false;
    if (!attr_set) {
        cudaFuncSetAttribute(reassemble_2q_kernel,
                             cudaFuncAttributeMaxDynamicSharedMemorySize, smem_bytes);
        attr_set = true;
    }
    reassemble_2q_kernel<<<B, TPB, smem_bytes>>>(patches, pos, out);
}

// round 11
// speedup vs baseline: 1.6483x; 1.0143x over previous
#include <cuda_runtime.h>

#define NP    64                 // patch size
#define CH    4                  // channels
#define PAD   192                // canvas
#define TPB   576                // 24 quad-cols x 24 rows
#define PLW   76                 // G plane width (zero borders both sides)
#define PLH   65                 // G rows: iy+1 in [0,64]
#define PLANE (PLW*PLH)          // 4940 floats
#define SMF   (CH*PLANE)         // 19760 floats = 79,040 B
#define GIN   (63*63)            // interior G positions per channel
#define GBRD  256                // border G positions per channel
#define ZVEC  (CH*PLH*4)         // border zero float4s: cols [0,7] & [68,75]
#define QC    24                 // quad columns per thread-row (x and x+96)
#define YSTEP (TPB/QC)           // 24
#define EITER (PAD/YSTEP)        // 8 eval iterations

// out[b,y,x] = sum_c bilinear(patch_c centered, y-64-dy_c, x-64-dx_c), zero fill.
// Integer pixel coords => bilinear weights constant per (b,c):
//   out(y,x) = G_c[y+oyc+1][...], G_c = 2x2 corr(patch_c, weights), in smem.
// Eval: two quads per thread 96px apart; per-channel y-window test is an
// OUTER branch (warp-near-uniform, skips ~65% of bodies entirely); per-quad
// x-validity is a lane-constant predicate inside.
__global__ __launch_bounds__(TPB, 2)
void reassemble_br_kernel(const float* __restrict__ patches,
                          const float* __restrict__ pos,
                          float* __restrict__ out)
{
    extern __shared__ float sm[];        // CH planes of [PLH][PLW]
    const int b   = blockIdx.x;
    const int tid = threadIdx.x;

    // ---- per-channel constants ----
    int   oxc[CH], shf[CH], off0[CH], oyc[CH];
    float w00[CH], w01[CH], w10[CH], w11[CH];
    const float* pb_pos = pos + (size_t)b * 2 * CH;
    #pragma unroll
    for (int c = 0; c < CH; c++) {
        const float dx = __ldg(pb_pos + c);
        const float dy = __ldg(pb_pos + CH + c);
        const float fx = -64.0f - dx;
        const float fy = -64.0f - dy;
        const float flx = floorf(fx), fly = floorf(fy);
        oxc[c] = (int)flx;
        oyc[c] = (int)fly;
        shf[c] = (4 - (oxc[c] & 3)) & 3;              // (oxc+shf) % 4 == 0
        off0[c] = c * PLANE + (oyc[c] + 1) * PLW + oxc[c] + shf[c] + 4;
        const float wx = fx - flx, wy = fy - fly;
        w00[c] = (1.0f - wx) * (1.0f - wy);
        w01[c] = wx * (1.0f - wy);
        w10[c] = (1.0f - wx) * wy;
        w11[c] = wx * wy;
    }

    // ---- zero border columns: cols [0,7] and [68,75] of every row ----
    {
        float4* smv = reinterpret_cast<float4*>(sm);
        #pragma unroll
        for (int i = tid; i < ZVEC; i += TPB) {        // 1040 vecs -> 2 iters
            const int plane = i / (PLH * 4);
            const int rem   = i - plane * (PLH * 4);
            const int row   = rem >> 2;
            const int v     = rem & 3;
            const int col4  = (v < 2) ? (v << 2) : (68 + ((v - 2) << 2));
            smv[(plane * PLANE + row * PLW + col4) >> 2] = make_float4(0.f, 0.f, 0.f, 0.f);
        }
    }
    __syncthreads();

    // ---- build G planes: interior (no tap guards) ----
    const float4* pin = reinterpret_cast<const float4*>(patches + (size_t)b * NP * NP * CH);
    for (int idx = tid; idx < GIN; idx += TPB) {       // ~6.9 iters
        const int r   = idx / 63;                      // 0..62
        const int gxi = idx - r * 63 + 1;              // 1..63
        const int gy  = r + 1;                         // 1..63
        const int ix  = gxi - 1;

        const float4 t00 = __ldg(pin + (gy - 1) * NP + ix);
        const float4 t01 = __ldg(pin + (gy - 1) * NP + ix + 1);
        const float4 t10 = __ldg(pin + gy * NP + ix);
        const float4 t11 = __ldg(pin + gy * NP + ix + 1);

        const int rb = gy * PLW + gxi + 3;
        sm[0 * PLANE + rb + shf[0]] = t00.x * w00[0] + t01.x * w01[0] + t10.x * w10[0] + t11.x * w11[0];
        sm[1 * PLANE + rb + shf[1]] = t00.y * w00[1] + t01.y * w01[1] + t10.y * w10[1] + t11.y * w11[1];
        sm[2 * PLANE + rb + shf[2]] = t00.z * w00[2] + t01.z * w01[2] + t10.z * w10[2] + t11.z * w11[2];
        sm[3 * PLANE + rb + shf[3]] = t00.w * w00[3] + t01.w * w01[3] + t10.w * w10[3] + t11.w * w11[3];
    }

    // ---- build G planes: 256 border positions (guarded taps) ----
    if (tid < GBRD) {
        int gy, gxi;
        if (tid < 65)       { gy = 0;         gxi = tid; }
        else if (tid < 130) { gy = 64;        gxi = tid - 65; }
        else if (tid < 193) { gy = tid - 129; gxi = 0;  }   // 1..63
        else                { gy = tid - 192; gxi = 64; }   // 1..63
        const int iy = gy - 1;
        const int ix = gxi - 1;
        const bool r0 = (gy >= 1), r1 = (gy <= 63);
        const bool c0 = (gxi >= 1), c1 = (gxi <= 63);
        const float4 z = make_float4(0.f, 0.f, 0.f, 0.f);
        const float4 t00 = (r0 && c0) ? __ldg(pin + iy * NP + ix)     : z;
        const float4 t01 = (r0 && c1) ? __ldg(pin + iy * NP + ix + 1) : z;
        const float4 t10 = (r1 && c0) ? __ldg(pin + gy * NP + ix)     : z;
        const float4 t11 = (r1 && c1) ? __ldg(pin + gy * NP + ix + 1) : z;

        const int rb = gy * PLW + gxi + 3;
        sm[0 * PLANE + rb + shf[0]] = t00.x * w00[0] + t01.x * w01[0] + t10.x * w10[0] + t11.x * w11[0];
        sm[1 * PLANE + rb + shf[1]] = t00.y * w00[1] + t01.y * w01[1] + t10.y * w10[1] + t11.y * w11[1];
        sm[2 * PLANE + rb + shf[2]] = t00.z * w00[2] + t01.z * w01[2] + t10.z * w10[2] + t11.z * w11[2];
        sm[3 * PLANE + rb + shf[3]] = t00.w * w00[3] + t01.w * w01[3] + t10.w * w10[3] + t11.w * w11[3];
    }
    __syncthreads();

    // ---- eval: two quads per thread (x0a and x0a+96), same y ----
    const int qcol = tid % QC;                          // 0..23
    const int x0a  = qcol * 4;                          // 0..92
    int y = tid / QC;                                   // 0..23

    // loop-invariant per channel: pure y-window low bound + x-validity flags
    int  ylo[CH], fba[CH];
    bool xaok[CH], xbok[CH];
    #pragma unroll
    for (int c = 0; c < CH; c++) {
        ylo[c]  = -1 - oyc[c];                          // iy = y+oy in [-1,63]
        xaok[c] = ((unsigned)(x0a + oxc[c] + 4) <= 71u);        // quad a
        xbok[c] = ((unsigned)(x0a + 96 + oxc[c] + 4) <= 71u);   // quad b
        fba[c]  = off0[c] + x0a;
    }

    float* po = out + (size_t)b * PAD * PAD + (size_t)y * PAD + x0a;
    int ywf = y * PLW;

    #pragma unroll
    for (int q = 0; q < EITER; q++) {
        float a0 = 0.f, a1 = 0.f, a2 = 0.f, a3 = 0.f;
        float b0 = 0.f, b1 = 0.f, b2 = 0.f, b3 = 0.f;

        #pragma unroll
        for (int c = 0; c < CH; c++) {
            // near-warp-uniform branch: skip channel when y outside window
            if ((unsigned)(y - ylo[c]) <= 64u) {
                const float* p = sm + fba[c] + ywf;
                if (xaok[c]) {
                    const float4 g = *reinterpret_cast<const float4*>(p);
                    a0 += g.x; a1 += g.y; a2 += g.z; a3 += g.w;
                }
                if (xbok[c]) {
                    const float4 g = *reinterpret_cast<const float4*>(p + 96);
                    b0 += g.x; b1 += g.y; b2 += g.z; b3 += g.w;
                }
            }
        }

        float4 oA; oA.x = a0; oA.y = a1; oA.z = a2; oA.w = a3;
        float4 oB; oB.x = b0; oB.y = b1; oB.z = b2; oB.w = b3;
        *reinterpret_cast<float4*>(po)      = oA;
        *reinterpret_cast<float4*>(po + 96) = oB;

        y   += YSTEP;
        ywf += YSTEP * PLW;
        po  += YSTEP * PAD;
    }
}

extern "C" void kernel_launch(void* const* d_in, const int* in_sizes, int n_in,
                              void* d_out, int out_size) {
    const float* patches = (const float*)d_in[0];   // (B, 64, 64, 4) fp32
    const float* pos     = (const float*)d_in[1];   // (B, 1, 2, 4)  fp32
    float* out           = (float*)d_out;           // (B, 192, 192, 1) fp32

    const int B = out_size / (PAD * PAD);           // 512
    const int smem_bytes = SMF * sizeof(float);     // 79,040 B
    static bool attr_set = false;
    if (!attr_set) {
        cudaFuncSetAttribute(reassemble_br_kernel,
                             cudaFuncAttributeMaxDynamicSharedMemorySize, smem_bytes);
        attr_set = true;
    }
    reassemble_br_kernel<<<B, TPB, smem_bytes>>>(patches, pos, out);
}